// round 8
// baseline (speedup 1.0000x reference)
#include <cuda_runtime.h>
#include <math_constants.h>

#define NB 64
#define NC 1000
#define HW 196
#define NF4 49
#define GY 8                              // blocks per batch
#define CPB (NC / GY)                     // 125 classes per block
#define NKW (GY * 8)                      // kp partials per batch (64)
#define C4L2E 5.770780163555852f          // 4 * log2(e)
#define RC4L2E 0.17328679513998632f       // 1 / C4L2E
#define LN2   0.6931471805599453f
#define L2E   1.4426950408889634f
#define CLIP2 (-19.931568569324174f)      // log2(1e-6)
#define DEADB (-24000.0f)                 // u bias for dead lane-slots: 2^u == 0

__device__ float g_abl[NB * NC];
__device__ float g_kpw[NB * NKW];
__device__ float g_ace[NB];
__device__ float g_kld[NB];
__device__ int   g_bcnt[NB];              // zero-init; reset by final block
__device__ int   g_done = 0;

__device__ __forceinline__ float ex2f(float x) {
    float r; asm("ex2.approx.f32 %0, %1;" : "=f"(r) : "f"(x)); return r;
}
__device__ __forceinline__ float warpSum(float v) {
#pragma unroll
    for (int o = 16; o; o >>= 1) v += __shfl_xor_sync(0xffffffffu, v, o);
    return v;
}
// two independent butterflies, interleaved so the SHFL latency chains overlap
__device__ __forceinline__ void warpSum2(float& a, float& b) {
#pragma unroll
    for (int o = 16; o; o >>= 1) {
        const float ta = __shfl_xor_sync(0xffffffffu, a, o);
        const float tb = __shfl_xor_sync(0xffffffffu, b, o);
        a += ta; b += tb;
    }
}
__device__ __forceinline__ float warpMax(float v) {
#pragma unroll
    for (int o = 16; o; o >>= 1) v = fmaxf(v, __shfl_xor_sync(0xffffffffu, v, o));
    return v;
}

// ---------------------------------------------------------------------------
// Fused kernel. grid=(NB, GY), block=256 (8 warps, 15-16 rows/warp).
// Phase A: warp-per-row; u = C4L2E*a + tnu. Shared tn/f arrays are PADDED to
// 64 float4 (slots 49..63 = DEADB / 0) so smem indexing is unconditional;
// global loads use a clamped slot index (in-bounds duplicate, arithmetically
// dead). Next row's loads prefetched before the current row's reductions.
// Phase B: 8th block per batch reduces 1000 abl + 64 kpw partials.
// Phase C: 64th batch-finisher -> scalar; resets counters (replay-safe).
// ---------------------------------------------------------------------------
__global__ __launch_bounds__(256, 6) void k1(const float* __restrict__ cams,
                                             const int* __restrict__ y0,
                                             const int* __restrict__ labels,
                                             float* __restrict__ out) {
    __shared__ float4 s_tn4[64];    // tnu = -C4L2E * target row (padded DEADB)
    __shared__ float4 s_f4[64];     // f2 = 2 * fg mask (padded 0)
    __shared__ float sh_mx[8];
    __shared__ float sh_se[8];
    __shared__ float sh_sa[8];
    __shared__ float sh_sk[8];
    __shared__ float s_red;
    __shared__ int s_flag;

    const int b = blockIdx.x;
    const int tid = threadIdx.x;
    const int label = __ldg(labels + b);
    const float* base = cams + (size_t)b * NC * HW;

    if (tid < HW) {
        ((float*)s_tn4)[tid] = -C4L2E * __ldg(base + (size_t)label * HW + tid);
        ((float*)s_f4)[tid]  = 2.0f * (float)__ldg(y0 + b * HW + tid);
    } else {
        ((float*)s_tn4)[tid] = DEADB;   // dead slots: 2^u == 0
        ((float*)s_f4)[tid]  = 0.0f;
    }
    __syncthreads();

    const int warp = tid >> 5;
    const int lane = tid & 31;
    const int sidx2 = 32 + lane;                  // smem slot (padded, safe)
    const int gidx2 = 32 + (lane < 17 ? lane : 16); // gmem slot (clamped)
    const float m1 = (lane < 17) ? 1.0f : 0.0f;   // masks |u| of dead slot

    // row-invariant fg count: n1 = 0.5 * sum(f2) (padding contributes 0)
    float n1;
    {
        const float4 fa = s_f4[lane];
        const float4 fb = s_f4[sidx2];
        n1 = 0.5f * ((fa.x + fa.y) + (fa.z + fa.w) +
                     (fb.x + fb.y) + (fb.z + fb.w));
        n1 = warpSum(n1);
    }

    const int c0 = blockIdx.y * CPB;
    const float4* p = (const float4*)(base + (size_t)(c0 + warp) * HW);
    const size_t rstep = (size_t)8 * NF4;
    float* gabl = g_abl + b * NC + c0 + warp;

    float kacc = 0.f;     // per-lane, across rows
    float L2sum = 0.f;    // per-row L2 accumulated (lane-uniform)

    float4 a0 = __ldg(p + lane);
    float4 a1 = __ldg(p + gidx2);

#pragma unroll 1
    for (int cl = warp; cl < CPB; cl += 8, gabl += 8) {
        // prefetch next row before this row's reduction chain
        const float4* pn = p + rstep;
        float4 b0, b1;
        const bool more = (cl + 8) < CPB;
        if (more) { b0 = __ldg(pn + lane); b1 = __ldg(pn + gidx2); }

        const float4 tn0 = s_tn4[lane];
        const float4 f0  = s_f4[lane];
        const float4 tn1 = s_tn4[sidx2];
        const float4 f1  = s_f4[sidx2];

        float u[8];
        float den = 0.f, sabs = 0.f, sfp = 0.f;

        u[0] = fmaf(C4L2E, a0.x, tn0.x); den += ex2f(u[0]);
        sabs += fabsf(u[0]); sfp = fmaf(f0.x, fmaxf(u[0], 0.f), sfp);
        u[1] = fmaf(C4L2E, a0.y, tn0.y); den += ex2f(u[1]);
        sabs += fabsf(u[1]); sfp = fmaf(f0.y, fmaxf(u[1], 0.f), sfp);
        u[2] = fmaf(C4L2E, a0.z, tn0.z); den += ex2f(u[2]);
        sabs += fabsf(u[2]); sfp = fmaf(f0.z, fmaxf(u[2], 0.f), sfp);
        u[3] = fmaf(C4L2E, a0.w, tn0.w); den += ex2f(u[3]);
        sabs += fabsf(u[3]); sfp = fmaf(f0.w, fmaxf(u[3], 0.f), sfp);

        u[4] = fmaf(C4L2E, a1.x, tn1.x); den += ex2f(u[4]);
        sabs = fmaf(m1, fabsf(u[4]), sabs); sfp = fmaf(f1.x, fmaxf(u[4], 0.f), sfp);
        u[5] = fmaf(C4L2E, a1.y, tn1.y); den += ex2f(u[5]);
        sabs = fmaf(m1, fabsf(u[5]), sabs); sfp = fmaf(f1.y, fmaxf(u[5], 0.f), sfp);
        u[6] = fmaf(C4L2E, a1.z, tn1.z); den += ex2f(u[6]);
        sabs = fmaf(m1, fabsf(u[6]), sabs); sfp = fmaf(f1.z, fmaxf(u[6], 0.f), sfp);
        u[7] = fmaf(C4L2E, a1.w, tn1.w); den += ex2f(u[7]);
        sabs = fmaf(m1, fabsf(u[7]), sabs); sfp = fmaf(f1.w, fmaxf(u[7], 0.f), sfp);

        float s1 = sabs - sfp;
        warpSum2(den, s1);                    // interleaved dual butterfly
        const float L2 = __log2f(den);
        const float Lc = L2 + CLIP2;
        L2sum += L2;

        kacc = fmaf(f0.x, fmaxf(u[0], Lc), kacc);
        kacc = fmaf(f0.y, fmaxf(u[1], Lc), kacc);
        kacc = fmaf(f0.z, fmaxf(u[2], Lc), kacc);
        kacc = fmaf(f0.w, fmaxf(u[3], Lc), kacc);
        kacc = fmaf(f1.x, fmaxf(u[4], Lc), kacc);
        kacc = fmaf(f1.y, fmaxf(u[5], Lc), kacc);
        kacc = fmaf(f1.z, fmaxf(u[6], Lc), kacc);
        kacc = fmaf(f1.w, fmaxf(u[7], Lc), kacc);

        if (lane == 0) *gabl = s1 * RC4L2E;

        p = pn; a0 = b0; a1 = b1;
    }

    // one kp reduction per warp for its whole chunk
    kacc = warpSum(kacc);
    if (lane == 0)
        g_kpw[b * NKW + blockIdx.y * 8 + warp] =
            -LN2 * (0.5f * kacc - n1 * L2sum);

    // ---------------- Phase B election: last block of this batch ------------
    __syncthreads();
    if (tid == 0) {
        __threadfence();                        // release g_abl/g_kpw stores
        s_flag = (atomicAdd(&g_bcnt[b], 1) == GY - 1);
    }
    __syncthreads();
    if (!s_flag) return;

    // ---------------- Phase B: per-batch reduction (L2-hot) -----------------
    __threadfence();                            // acquire peers' stores
    const float* abl = g_abl + b * NC;
    const float* kwp = g_kpw + b * NKW;

    float mx = -CUDART_INF_F;
    for (int c = tid; c < NC; c += 256) mx = fmaxf(mx, abl[c]);
    mx = warpMax(mx);
    if (lane == 0) sh_mx[warp] = mx;
    __syncthreads();
    if (warp == 0) {
        float m2 = (lane < 8) ? sh_mx[lane] : -CUDART_INF_F;
        m2 = warpMax(m2);
        if (lane == 0) s_red = m2;
    }
    __syncthreads();
    const float bmax = s_red;

    float se = 0.f, sa = 0.f;
    for (int c = tid; c < NC; c += 256) {
        const float a = abl[c];
        se += ex2f((a - bmax) * L2E);
        sa += a;
    }
    float sk = (tid < NKW) ? kwp[tid] : 0.f;
    se = warpSum(se); sa = warpSum(sa); sk = warpSum(sk);
    if (lane == 0) { sh_se[warp] = se; sh_sa[warp] = sa; sh_sk[warp] = sk; }
    __syncthreads();

    if (tid == 0) {
        float se_t = 0.f, sa_t = 0.f, sk_t = 0.f;
        for (int i = 0; i < 8; i++) { se_t += sh_se[i]; sa_t += sh_sa[i]; sk_t += sh_sk[i]; }
        const float L = __logf(se_t);
        const float al = abl[label];
        const float ace = -(0.9f * (al - bmax - L) +
                            1e-4f * (sa_t - (float)NC * (bmax + L)));
        float p1 = 0.f;
        if (n1 > 0.f) p1 = 1.f / (n1 + ((float)HW - n1) * __expf(-10.f));
        g_ace[b] = ace;
        g_kld[b] = p1 * sk_t;
        __threadfence();
        s_flag = (atomicAdd(&g_done, 1) == NB - 1);
    }
    __syncthreads();
    if (!s_flag) return;

    // ---------------- Phase C: final 64 -> 1 + counter reset ----------------
    if (warp == 0) {
        __threadfence();                        // acquire all g_ace/g_kld
        float a = g_ace[lane] + g_ace[lane + 32];
        float k = g_kld[lane] + g_kld[lane + 32];
        a = warpSum(a);
        k = warpSum(k);
        g_bcnt[lane] = 0;
        g_bcnt[lane + 32] = 0;
        if (lane == 0) {
            out[0] = (a + 0.5f * k) * (1.0f / NB);
            g_done = 0;
        }
    }
}

extern "C" void kernel_launch(void* const* d_in, const int* in_sizes, int n_in,
                              void* d_out, int out_size) {
    const float* cams  = (const float*)d_in[0];
    const int* y0      = (const int*)d_in[1];
    const int* labels  = (const int*)d_in[2];
    float* out = (float*)d_out;

    k1<<<dim3(NB, GY), 256>>>(cams, y0, labels, out);
}

// round 9
// speedup vs baseline: 1.1006x; 1.1006x over previous
#include <cuda_runtime.h>
#include <math_constants.h>

#define NB 64
#define NC 1000
#define HW 196
#define NF4 49
#define GY 25                             // blocks per batch
#define CPB (NC / GY)                     // 40 classes per block -> 5 rows/warp
#define NKW (GY * 8)                      // kp partials per batch (200)
#define C4L2E 5.770780163555852f          // 4 * log2(e)
#define RC4L2E 0.17328679513998632f       // 1 / C4L2E
#define LN2   0.6931471805599453f
#define L2E   1.4426950408889634f
#define CLIP2 (-19.931568569324174f)      // log2(1e-6)
#define DEADB (-24000.0f)                 // u bias for dead lane-slots: 2^u == 0

__device__ float g_abl[NB * NC];
__device__ float g_kpw[NB * NKW];
__device__ float g_ace[NB];
__device__ float g_kld[NB];
__device__ int   g_bcnt[NB];              // zero-init; reset by final block
__device__ int   g_done = 0;

__device__ __forceinline__ float ex2f(float x) {
    float r; asm("ex2.approx.f32 %0, %1;" : "=f"(r) : "f"(x)); return r;
}
__device__ __forceinline__ float warpSum(float v) {
#pragma unroll
    for (int o = 16; o; o >>= 1) v += __shfl_xor_sync(0xffffffffu, v, o);
    return v;
}
// two independent butterflies, interleaved so the SHFL latency chains overlap
__device__ __forceinline__ void warpSum2(float& a, float& b) {
#pragma unroll
    for (int o = 16; o; o >>= 1) {
        const float ta = __shfl_xor_sync(0xffffffffu, a, o);
        const float tb = __shfl_xor_sync(0xffffffffu, b, o);
        a += ta; b += tb;
    }
}
__device__ __forceinline__ float warpMax(float v) {
#pragma unroll
    for (int o = 16; o; o >>= 1) v = fmaxf(v, __shfl_xor_sync(0xffffffffu, v, o));
    return v;
}

// ---------------------------------------------------------------------------
// Fused kernel. grid=(NB, GY), block=256 (8 warps, exactly 5 rows/warp).
// Phase A (u-direct): u = C4L2E*a + tnu. tn/f register-resident (R7 config).
// Loop bound is compile-time (5 iters) with NO unroll pragma so ptxas can
// software-pipeline the LDG.128s across rows. den & abl butterflies are
// interleaved (warpSum2). kp accumulates across rows; one butterfly at end.
// Phase B: 25th block per batch reduces 1000 abl + 200 kpw partials.
// Phase C: 64th batch-finisher -> scalar; resets counters (replay-safe).
// All reduction orders fixed -> deterministic.
// ---------------------------------------------------------------------------
__global__ __launch_bounds__(256, 6) void k1(const float* __restrict__ cams,
                                             const int* __restrict__ y0,
                                             const int* __restrict__ labels,
                                             float* __restrict__ out) {
    __shared__ float4 s_tn4[NF4];   // tnu = -C4L2E * target row
    __shared__ float4 s_f4[NF4];    // f2 = 2 * fg mask
    __shared__ float sh_mx[8];
    __shared__ float sh_se[8];
    __shared__ float sh_sa[8];
    __shared__ float sh_sk[8];
    __shared__ float s_red;
    __shared__ int s_flag;

    const int b = blockIdx.x;
    const int tid = threadIdx.x;
    const int label = __ldg(labels + b);
    const float* base = cams + (size_t)b * NC * HW;

    if (tid < HW) {
        ((float*)s_tn4)[tid] = -C4L2E * __ldg(base + (size_t)label * HW + tid);
        ((float*)s_f4)[tid]  = 2.0f * (float)__ldg(y0 + b * HW + tid);
    }
    __syncthreads();

    const int warp = tid >> 5;
    const int lane = tid & 31;
    const bool live = lane < (NF4 - 32);
    const int idx2 = 32 + (live ? lane : 16);     // clamped (slot 48 valid)
    const float m1 = live ? 1.0f : 0.0f;

    const float4 tnu0 = s_tn4[lane];
    const float4 f0   = s_f4[lane];               // f2 values
    float4 tnu1, f1;
    if (live) { tnu1 = s_tn4[idx2]; f1 = s_f4[idx2]; }
    else {
        tnu1 = make_float4(DEADB, DEADB, DEADB, DEADB);
        f1   = make_float4(0.f, 0.f, 0.f, 0.f);
    }

    // row-invariant fg count: n1 = 0.5 * sum(f2)
    float n1 = 0.5f * ((f0.x + f0.y) + (f0.z + f0.w) +
                       (f1.x + f1.y) + (f1.z + f1.w));
    n1 = warpSum(n1);

    const int c0 = blockIdx.y * CPB;
    const float4* row4 = (const float4*)(base + (size_t)(c0 + warp) * HW);
    const size_t rstep = (size_t)8 * NF4;

    float kacc = 0.f;     // per-lane, across rows
    float L2sum = 0.f;    // per-row L2 accumulated (lane-uniform)

    // exactly 5 iterations (CPB=40, stride 8) — let ptxas pipeline the loads
    for (int cl = warp; cl < CPB; cl += 8, row4 += rstep) {
        const float4 a0 = __ldg(row4 + lane);
        const float4 a1 = __ldg(row4 + idx2);

        float u[8];
        float den = 0.f, sabs = 0.f, sfp = 0.f;

        u[0] = fmaf(C4L2E, a0.x, tnu0.x); den += ex2f(u[0]);
        sabs += fabsf(u[0]); sfp = fmaf(f0.x, fmaxf(u[0], 0.f), sfp);
        u[1] = fmaf(C4L2E, a0.y, tnu0.y); den += ex2f(u[1]);
        sabs += fabsf(u[1]); sfp = fmaf(f0.y, fmaxf(u[1], 0.f), sfp);
        u[2] = fmaf(C4L2E, a0.z, tnu0.z); den += ex2f(u[2]);
        sabs += fabsf(u[2]); sfp = fmaf(f0.z, fmaxf(u[2], 0.f), sfp);
        u[3] = fmaf(C4L2E, a0.w, tnu0.w); den += ex2f(u[3]);
        sabs += fabsf(u[3]); sfp = fmaf(f0.w, fmaxf(u[3], 0.f), sfp);

        u[4] = fmaf(C4L2E, a1.x, tnu1.x); den += ex2f(u[4]);
        sabs = fmaf(m1, fabsf(u[4]), sabs); sfp = fmaf(f1.x, fmaxf(u[4], 0.f), sfp);
        u[5] = fmaf(C4L2E, a1.y, tnu1.y); den += ex2f(u[5]);
        sabs = fmaf(m1, fabsf(u[5]), sabs); sfp = fmaf(f1.y, fmaxf(u[5], 0.f), sfp);
        u[6] = fmaf(C4L2E, a1.z, tnu1.z); den += ex2f(u[6]);
        sabs = fmaf(m1, fabsf(u[6]), sabs); sfp = fmaf(f1.z, fmaxf(u[6], 0.f), sfp);
        u[7] = fmaf(C4L2E, a1.w, tnu1.w); den += ex2f(u[7]);
        sabs = fmaf(m1, fabsf(u[7]), sabs); sfp = fmaf(f1.w, fmaxf(u[7], 0.f), sfp);

        float s1 = sabs - sfp;
        warpSum2(den, s1);                    // interleaved dual butterfly
        const float L2 = __log2f(den);
        const float Lc = L2 + CLIP2;
        L2sum += L2;

        kacc = fmaf(f0.x, fmaxf(u[0], Lc), kacc);
        kacc = fmaf(f0.y, fmaxf(u[1], Lc), kacc);
        kacc = fmaf(f0.z, fmaxf(u[2], Lc), kacc);
        kacc = fmaf(f0.w, fmaxf(u[3], Lc), kacc);
        kacc = fmaf(f1.x, fmaxf(u[4], Lc), kacc);
        kacc = fmaf(f1.y, fmaxf(u[5], Lc), kacc);
        kacc = fmaf(f1.z, fmaxf(u[6], Lc), kacc);
        kacc = fmaf(f1.w, fmaxf(u[7], Lc), kacc);

        if (lane == 0) g_abl[b * NC + c0 + cl] = s1 * RC4L2E;
    }

    // one kp reduction per warp for its whole chunk
    kacc = warpSum(kacc);
    if (lane == 0)
        g_kpw[b * NKW + blockIdx.y * 8 + warp] =
            -LN2 * (0.5f * kacc - n1 * L2sum);

    // ---------------- Phase B election: last block of this batch ------------
    __syncthreads();
    if (tid == 0) {
        __threadfence();                        // release g_abl/g_kpw stores
        s_flag = (atomicAdd(&g_bcnt[b], 1) == GY - 1);
    }
    __syncthreads();
    if (!s_flag) return;

    // ---------------- Phase B: per-batch reduction (L2-hot) -----------------
    __threadfence();                            // acquire peers' stores
    const float* abl = g_abl + b * NC;
    const float* kwp = g_kpw + b * NKW;

    float mx = -CUDART_INF_F;
    for (int c = tid; c < NC; c += 256) mx = fmaxf(mx, abl[c]);
    mx = warpMax(mx);
    if (lane == 0) sh_mx[warp] = mx;
    __syncthreads();
    if (warp == 0) {
        float m2 = (lane < 8) ? sh_mx[lane] : -CUDART_INF_F;
        m2 = warpMax(m2);
        if (lane == 0) s_red = m2;
    }
    __syncthreads();
    const float bmax = s_red;

    float se = 0.f, sa = 0.f;
    for (int c = tid; c < NC; c += 256) {
        const float a = abl[c];
        se += ex2f((a - bmax) * L2E);
        sa += a;
    }
    float sk = (tid < NKW) ? kwp[tid] : 0.f;
    se = warpSum(se); sa = warpSum(sa); sk = warpSum(sk);
    if (lane == 0) { sh_se[warp] = se; sh_sa[warp] = sa; sh_sk[warp] = sk; }
    __syncthreads();

    if (tid == 0) {
        float se_t = 0.f, sa_t = 0.f, sk_t = 0.f;
        for (int i = 0; i < 8; i++) { se_t += sh_se[i]; sa_t += sh_sa[i]; sk_t += sh_sk[i]; }
        const float L = __logf(se_t);
        const float al = abl[label];
        const float ace = -(0.9f * (al - bmax - L) +
                            1e-4f * (sa_t - (float)NC * (bmax + L)));
        float p1 = 0.f;
        if (n1 > 0.f) p1 = 1.f / (n1 + ((float)HW - n1) * __expf(-10.f));
        g_ace[b] = ace;
        g_kld[b] = p1 * sk_t;
        __threadfence();
        s_flag = (atomicAdd(&g_done, 1) == NB - 1);
    }
    __syncthreads();
    if (!s_flag) return;

    // ---------------- Phase C: final 64 -> 1 + counter reset ----------------
    if (warp == 0) {
        __threadfence();                        // acquire all g_ace/g_kld
        float a = g_ace[lane] + g_ace[lane + 32];
        float k = g_kld[lane] + g_kld[lane + 32];
        a = warpSum(a);
        k = warpSum(k);
        g_bcnt[lane] = 0;
        g_bcnt[lane + 32] = 0;
        if (lane == 0) {
            out[0] = (a + 0.5f * k) * (1.0f / NB);
            g_done = 0;
        }
    }
}

extern "C" void kernel_launch(void* const* d_in, const int* in_sizes, int n_in,
                              void* d_out, int out_size) {
    const float* cams  = (const float*)d_in[0];
    const int* y0      = (const int*)d_in[1];
    const int* labels  = (const int*)d_in[2];
    float* out = (float*)d_out;

    k1<<<dim3(NB, GY), 256>>>(cams, y0, labels, out);
}

// round 10
// speedup vs baseline: 1.1250x; 1.0221x over previous
#include <cuda_runtime.h>
#include <math_constants.h>

#define NB 64
#define NC 1000
#define HW 196
#define NF4 49
#define GY 25                             // blocks per batch
#define CPB (NC / GY)                     // 40 classes per block
#define NKW (GY * 8)                      // kp partials per batch (200)
#define C4L2E 5.770780163555852f          // 4 * log2(e)
#define RC4L2E 0.17328679513998632f       // 1 / C4L2E
#define LN2   0.6931471805599453f
#define L2E   1.4426950408889634f
#define CLIP2 (-19.931568569324174f)      // log2(1e-6)
#define DEADB (-24000.0f)                 // u bias for dead lane-slots: 2^u == 0

__device__ float g_abl[NB * NC];
__device__ float g_kpw[NB * NKW];
__device__ float g_ace[NB];
__device__ float g_kld[NB];
__device__ int   g_bcnt[NB];              // zero-init; reset by final block
__device__ int   g_done = 0;

__device__ __forceinline__ float ex2f(float x) {
    float r; asm("ex2.approx.f32 %0, %1;" : "=f"(r) : "f"(x)); return r;
}
__device__ __forceinline__ float warpSum(float v) {
#pragma unroll
    for (int o = 16; o; o >>= 1) v += __shfl_xor_sync(0xffffffffu, v, o);
    return v;
}
// four independent butterflies, interleaved: SHFL latencies overlap
__device__ __forceinline__ void warpSum4(float& a, float& b, float& c, float& d) {
#pragma unroll
    for (int o = 16; o; o >>= 1) {
        const float ta = __shfl_xor_sync(0xffffffffu, a, o);
        const float tb = __shfl_xor_sync(0xffffffffu, b, o);
        const float tc = __shfl_xor_sync(0xffffffffu, c, o);
        const float td = __shfl_xor_sync(0xffffffffu, d, o);
        a += ta; b += tb; c += tc; d += td;
    }
}
__device__ __forceinline__ float warpMax(float v) {
#pragma unroll
    for (int o = 16; o; o >>= 1) v = fmaxf(v, __shfl_xor_sync(0xffffffffu, v, o));
    return v;
}

// process one row's element-wise work given loaded data
#define ROW_BODY(aa0, aa1, uu, dd, ss) do {                                     \
    float _sabs = 0.f, _sfp = 0.f;                                              \
    uu[0] = fmaf(C4L2E, aa0.x, tnu0.x); dd += ex2f(uu[0]);                      \
    _sabs += fabsf(uu[0]); _sfp = fmaf(f0.x, fmaxf(uu[0], 0.f), _sfp);          \
    uu[1] = fmaf(C4L2E, aa0.y, tnu0.y); dd += ex2f(uu[1]);                      \
    _sabs += fabsf(uu[1]); _sfp = fmaf(f0.y, fmaxf(uu[1], 0.f), _sfp);          \
    uu[2] = fmaf(C4L2E, aa0.z, tnu0.z); dd += ex2f(uu[2]);                      \
    _sabs += fabsf(uu[2]); _sfp = fmaf(f0.z, fmaxf(uu[2], 0.f), _sfp);          \
    uu[3] = fmaf(C4L2E, aa0.w, tnu0.w); dd += ex2f(uu[3]);                      \
    _sabs += fabsf(uu[3]); _sfp = fmaf(f0.w, fmaxf(uu[3], 0.f), _sfp);          \
    uu[4] = fmaf(C4L2E, aa1.x, tnu1.x); dd += ex2f(uu[4]);                      \
    _sabs = fmaf(m1, fabsf(uu[4]), _sabs); _sfp = fmaf(f1.x, fmaxf(uu[4], 0.f), _sfp); \
    uu[5] = fmaf(C4L2E, aa1.y, tnu1.y); dd += ex2f(uu[5]);                      \
    _sabs = fmaf(m1, fabsf(uu[5]), _sabs); _sfp = fmaf(f1.y, fmaxf(uu[5], 0.f), _sfp); \
    uu[6] = fmaf(C4L2E, aa1.z, tnu1.z); dd += ex2f(uu[6]);                      \
    _sabs = fmaf(m1, fabsf(uu[6]), _sabs); _sfp = fmaf(f1.z, fmaxf(uu[6], 0.f), _sfp); \
    uu[7] = fmaf(C4L2E, aa1.w, tnu1.w); dd += ex2f(uu[7]);                      \
    _sabs = fmaf(m1, fabsf(uu[7]), _sabs); _sfp = fmaf(f1.w, fmaxf(uu[7], 0.f), _sfp); \
    ss = _sabs - _sfp;                                                          \
} while (0)

#define KACC_BODY(uu, Lc) do {                                                  \
    kacc = fmaf(f0.x, fmaxf(uu[0], Lc), kacc);                                  \
    kacc = fmaf(f0.y, fmaxf(uu[1], Lc), kacc);                                  \
    kacc = fmaf(f0.z, fmaxf(uu[2], Lc), kacc);                                  \
    kacc = fmaf(f0.w, fmaxf(uu[3], Lc), kacc);                                  \
    kacc = fmaf(f1.x, fmaxf(uu[4], Lc), kacc);                                  \
    kacc = fmaf(f1.y, fmaxf(uu[5], Lc), kacc);                                  \
    kacc = fmaf(f1.z, fmaxf(uu[6], Lc), kacc);                                  \
    kacc = fmaf(f1.w, fmaxf(uu[7], Lc), kacc);                                  \
} while (0)

// ---------------------------------------------------------------------------
// Fused kernel. grid=(NB, GY), block=256.
// Phase A: each warp processes PAIRS of adjacent rows per iteration (2-row
// ILP): warp w owns rows {2w, 2w+1}, stride 16 over CPB=40. Four butterflies
// (denA, denB, s1A, s1B) interleave in one SHFL chain. Reg budget raised to
// 64 (__launch_bounds__(256,4)) to hold both rows' u[].
// Phase B: 25th block per batch reduces 1000 abl + 200 kpw partials.
// Phase C: 64th batch-finisher -> scalar; resets counters (replay-safe).
// ---------------------------------------------------------------------------
__global__ __launch_bounds__(256, 4) void k1(const float* __restrict__ cams,
                                             const int* __restrict__ y0,
                                             const int* __restrict__ labels,
                                             float* __restrict__ out) {
    __shared__ float4 s_tn4[NF4];   // tnu = -C4L2E * target row
    __shared__ float4 s_f4[NF4];    // f2 = 2 * fg mask
    __shared__ float sh_mx[8];
    __shared__ float sh_se[8];
    __shared__ float sh_sa[8];
    __shared__ float sh_sk[8];
    __shared__ float s_red;
    __shared__ int s_flag;

    const int b = blockIdx.x;
    const int tid = threadIdx.x;
    const int label = __ldg(labels + b);
    const float* base = cams + (size_t)b * NC * HW;

    if (tid < HW) {
        ((float*)s_tn4)[tid] = -C4L2E * __ldg(base + (size_t)label * HW + tid);
        ((float*)s_f4)[tid]  = 2.0f * (float)__ldg(y0 + b * HW + tid);
    }
    __syncthreads();

    const int warp = tid >> 5;
    const int lane = tid & 31;
    const bool live = lane < (NF4 - 32);
    const int idx2 = 32 + (live ? lane : 16);     // clamped (slot 48 valid)
    const float m1 = live ? 1.0f : 0.0f;

    const float4 tnu0 = s_tn4[lane];
    const float4 f0   = s_f4[lane];               // f2 values
    float4 tnu1, f1;
    if (live) { tnu1 = s_tn4[idx2]; f1 = s_f4[idx2]; }
    else {
        tnu1 = make_float4(DEADB, DEADB, DEADB, DEADB);
        f1   = make_float4(0.f, 0.f, 0.f, 0.f);
    }

    // row-invariant fg count: n1 = 0.5 * sum(f2)
    float n1 = 0.5f * ((f0.x + f0.y) + (f0.z + f0.w) +
                       (f1.x + f1.y) + (f1.z + f1.w));
    n1 = warpSum(n1);

    const int c0 = blockIdx.y * CPB;
    float kacc = 0.f;     // per-lane, across rows
    float L2sum = 0.f;    // per-row L2 accumulated (lane-uniform)

    // pair loop: rows {pb, pb+1}, pb = 2*warp, 2*warp+16, 2*warp+32 (<CPB)
#pragma unroll 1
    for (int pb = 2 * warp; pb < CPB; pb += 16) {
        const float4* rowA = (const float4*)(base + (size_t)(c0 + pb) * HW);
        const float4* rowB = rowA + NF4;

        const float4 aA0 = __ldg(rowA + lane);
        const float4 aA1 = __ldg(rowA + idx2);
        const float4 aB0 = __ldg(rowB + lane);
        const float4 aB1 = __ldg(rowB + idx2);

        float uA[8], uB[8];
        float denA = 0.f, denB = 0.f, s1A, s1B;

        ROW_BODY(aA0, aA1, uA, denA, s1A);
        ROW_BODY(aB0, aB1, uB, denB, s1B);

        warpSum4(denA, denB, s1A, s1B);       // 4-way interleaved butterfly

        const float L2A = __log2f(denA);
        const float L2B = __log2f(denB);
        L2sum += L2A + L2B;
        const float LcA = L2A + CLIP2;
        const float LcB = L2B + CLIP2;

        KACC_BODY(uA, LcA);
        KACC_BODY(uB, LcB);

        if (lane == 0) {
            g_abl[b * NC + c0 + pb]     = s1A * RC4L2E;
            g_abl[b * NC + c0 + pb + 1] = s1B * RC4L2E;
        }
    }

    // one kp reduction per warp for its whole chunk
    kacc = warpSum(kacc);
    if (lane == 0)
        g_kpw[b * NKW + blockIdx.y * 8 + warp] =
            -LN2 * (0.5f * kacc - n1 * L2sum);

    // ---------------- Phase B election: last block of this batch ------------
    __syncthreads();
    if (tid == 0) {
        __threadfence();                        // release g_abl/g_kpw stores
        s_flag = (atomicAdd(&g_bcnt[b], 1) == GY - 1);
    }
    __syncthreads();
    if (!s_flag) return;

    // ---------------- Phase B: per-batch reduction (L2-hot) -----------------
    __threadfence();                            // acquire peers' stores
    const float* abl = g_abl + b * NC;
    const float* kwp = g_kpw + b * NKW;

    float mx = -CUDART_INF_F;
    for (int c = tid; c < NC; c += 256) mx = fmaxf(mx, abl[c]);
    mx = warpMax(mx);
    if (lane == 0) sh_mx[warp] = mx;
    __syncthreads();
    if (warp == 0) {
        float m2 = (lane < 8) ? sh_mx[lane] : -CUDART_INF_F;
        m2 = warpMax(m2);
        if (lane == 0) s_red = m2;
    }
    __syncthreads();
    const float bmax = s_red;

    float se = 0.f, sa = 0.f;
    for (int c = tid; c < NC; c += 256) {
        const float a = abl[c];
        se += ex2f((a - bmax) * L2E);
        sa += a;
    }
    float sk = (tid < NKW) ? kwp[tid] : 0.f;
    se = warpSum(se); sa = warpSum(sa); sk = warpSum(sk);
    if (lane == 0) { sh_se[warp] = se; sh_sa[warp] = sa; sh_sk[warp] = sk; }
    __syncthreads();

    if (tid == 0) {
        float se_t = 0.f, sa_t = 0.f, sk_t = 0.f;
        for (int i = 0; i < 8; i++) { se_t += sh_se[i]; sa_t += sh_sa[i]; sk_t += sh_sk[i]; }
        const float L = __logf(se_t);
        const float al = abl[label];
        const float ace = -(0.9f * (al - bmax - L) +
                            1e-4f * (sa_t - (float)NC * (bmax + L)));
        float p1 = 0.f;
        if (n1 > 0.f) p1 = 1.f / (n1 + ((float)HW - n1) * __expf(-10.f));
        g_ace[b] = ace;
        g_kld[b] = p1 * sk_t;
        __threadfence();
        s_flag = (atomicAdd(&g_done, 1) == NB - 1);
    }
    __syncthreads();
    if (!s_flag) return;

    // ---------------- Phase C: final 64 -> 1 + counter reset ----------------
    if (warp == 0) {
        __threadfence();                        // acquire all g_ace/g_kld
        float a = g_ace[lane] + g_ace[lane + 32];
        float k = g_kld[lane] + g_kld[lane + 32];
        a = warpSum(a);
        k = warpSum(k);
        g_bcnt[lane] = 0;
        g_bcnt[lane + 32] = 0;
        if (lane == 0) {
            out[0] = (a + 0.5f * k) * (1.0f / NB);
            g_done = 0;
        }
    }
}

extern "C" void kernel_launch(void* const* d_in, const int* in_sizes, int n_in,
                              void* d_out, int out_size) {
    const float* cams  = (const float*)d_in[0];
    const int* y0      = (const int*)d_in[1];
    const int* labels  = (const int*)d_in[2];
    float* out = (float*)d_out;

    k1<<<dim3(NB, GY), 256>>>(cams, y0, labels, out);
}